// round 2
// baseline (speedup 1.0000x reference)
#include <cuda_runtime.h>
#include <math_constants.h>

#define B_ROWS   16384
#define DIM      768
#define NPROMPT  8192
#define TOPK     5
#define NTILE    64          // NPROMPT / BN

// Partial top-k scratch: [B_ROWS][NTILE][TOPK] values + indices (~42 MB total)
__device__ float g_pval[(size_t)B_ROWS * NTILE * TOPK];
__device__ int   g_pidx[(size_t)B_ROWS * NTILE * TOPK];

#define BM 128
#define BN 128
#define BK 16
#define TM 8
#define TN 8

// Insert (v, ix) into a register-resident (val desc, idx asc) sorted top-5.
// All indices are compile-time constants after unrolling -> stays in registers.
__device__ __forceinline__ void insert5(float (&tv)[TOPK], int (&tix)[TOPK],
                                        float v, int ix)
{
    bool enter = (v > tv[TOPK - 1]) || (v == tv[TOPK - 1] && ix < tix[TOPK - 1]);
    if (enter) {
        tv[TOPK - 1] = v;
        tix[TOPK - 1] = ix;
        #pragma unroll
        for (int k = TOPK - 1; k > 0; k--) {
            bool sw = (tv[k] > tv[k - 1]) ||
                      (tv[k] == tv[k - 1] && tix[k] < tix[k - 1]);
            if (sw) {
                float t = tv[k];  tv[k] = tv[k - 1];  tv[k - 1] = t;
                int   ti = tix[k]; tix[k] = tix[k - 1]; tix[k - 1] = ti;
            }
        }
    }
}

// ---------------------------------------------------------------------------
// Kernel A: scores tile = V @ W^T + b, fused per-row top-5 over the 128-col
// tile, writing TOPK candidates per (row, tile) to scratch.
// ---------------------------------------------------------------------------
__global__ __launch_bounds__(256, 2)
void gemm_topk_kernel(const float* __restrict__ V,
                      const float* __restrict__ W,
                      const float* __restrict__ bias)
{
    __shared__ float As[BK][BM];
    __shared__ float Bs[BK][BN];

    const int bm  = blockIdx.y * BM;
    const int bn  = blockIdx.x * BN;
    const int tid = threadIdx.x;

    const int tm = (tid / 16) * TM;    // group of 16 lanes owns 8 rows
    const int tn = (tid % 16) * TN;    // lane owns 8 cols

    float acc[TM][TN];
    #pragma unroll
    for (int i = 0; i < TM; i++)
        #pragma unroll
        for (int j = 0; j < TN; j++)
            acc[i][j] = 0.0f;

    for (int k0 = 0; k0 < DIM; k0 += BK) {
        #pragma unroll
        for (int l = 0; l < 2; l++) {
            int idx = tid + l * 256;
            int r   = idx >> 2;
            int kq  = (idx & 3) * 4;
            float4 v = *reinterpret_cast<const float4*>(
                &V[(size_t)(bm + r) * DIM + k0 + kq]);
            As[kq + 0][r] = v.x;  As[kq + 1][r] = v.y;
            As[kq + 2][r] = v.z;  As[kq + 3][r] = v.w;
        }
        #pragma unroll
        for (int l = 0; l < 2; l++) {
            int idx = tid + l * 256;
            int r   = idx >> 2;
            int kq  = (idx & 3) * 4;
            float4 v = *reinterpret_cast<const float4*>(
                &W[(size_t)(bn + r) * DIM + k0 + kq]);
            Bs[kq + 0][r] = v.x;  Bs[kq + 1][r] = v.y;
            Bs[kq + 2][r] = v.z;  Bs[kq + 3][r] = v.w;
        }
        __syncthreads();

        #pragma unroll
        for (int kk = 0; kk < BK; kk++) {
            float a[TM], bb[TN];
            #pragma unroll
            for (int i = 0; i < TM; i++) a[i]  = As[kk][tm + i];
            #pragma unroll
            for (int j = 0; j < TN; j++) bb[j] = Bs[kk][tn + j];
            #pragma unroll
            for (int i = 0; i < TM; i++)
                #pragma unroll
                for (int j = 0; j < TN; j++)
                    acc[i][j] = fmaf(a[i], bb[j], acc[i][j]);
        }
        __syncthreads();
    }

    // ---- epilogue: bias + per-row top-5 over this 128-col tile ----
    float br[TN];
    #pragma unroll
    for (int j = 0; j < TN; j++) br[j] = bias[bn + tn + j];

    const unsigned FULL = 0xffffffffu;

    #pragma unroll
    for (int i = 0; i < TM; i++) {
        float tv[TOPK];
        int   tix[TOPK];
        #pragma unroll
        for (int k = 0; k < TOPK; k++) { tv[k] = -CUDART_INF_F; tix[k] = 0x7fffffff; }

        #pragma unroll
        for (int j = 0; j < TN; j++) {
            insert5(tv, tix, acc[i][j] + br[j], bn + tn + j);
        }

        // butterfly merge across the 16 lanes of this row-group
        #pragma unroll
        for (int off = 1; off < 16; off <<= 1) {
            float ov[TOPK];
            int   oi[TOPK];
            #pragma unroll
            for (int k = 0; k < TOPK; k++) {
                ov[k] = __shfl_xor_sync(FULL, tv[k], off);
                oi[k] = __shfl_xor_sync(FULL, tix[k], off);
            }
            #pragma unroll
            for (int k = 0; k < TOPK; k++) insert5(tv, tix, ov[k], oi[k]);
        }

        if ((tid & 15) == 0) {
            int row = bm + tm + i;
            size_t base = ((size_t)row * NTILE + blockIdx.x) * TOPK;
            #pragma unroll
            for (int k = 0; k < TOPK; k++) {
                g_pval[base + k] = tv[k];
                g_pidx[base + k] = tix[k];
            }
        }
    }
}

// ---------------------------------------------------------------------------
// Kernel B: per row, merge 64 candidate lists (320 entries) -> global top-5,
// softmax, weighted gather-combine from prompt_pool. One 256-thread CTA/row.
// ---------------------------------------------------------------------------
__global__ __launch_bounds__(256)
void merge_combine_kernel(const float* __restrict__ pool,
                          float* __restrict__ out)
{
    const int row = blockIdx.x;
    const int tid = threadIdx.x;

    __shared__ float s_topv[TOPK];
    __shared__ int   s_topi[TOPK];

    if (tid < 32) {
        const unsigned FULL = 0xffffffffu;
        float tv[TOPK];
        int   tix[TOPK];
        #pragma unroll
        for (int k = 0; k < TOPK; k++) { tv[k] = -CUDART_INF_F; tix[k] = 0x7fffffff; }

        size_t rbase = (size_t)row * NTILE * TOPK;
        // lane t handles tiles t and t+32
        #pragma unroll
        for (int h = 0; h < 2; h++) {
            size_t base = rbase + (size_t)(tid + h * 32) * TOPK;
            #pragma unroll
            for (int k = 0; k < TOPK; k++) {
                insert5(tv, tix, g_pval[base + k], g_pidx[base + k]);
            }
        }
        // butterfly merge across 32 lanes
        #pragma unroll
        for (int off = 1; off < 32; off <<= 1) {
            float ov[TOPK];
            int   oi[TOPK];
            #pragma unroll
            for (int k = 0; k < TOPK; k++) {
                ov[k] = __shfl_xor_sync(FULL, tv[k], off);
                oi[k] = __shfl_xor_sync(FULL, tix[k], off);
            }
            #pragma unroll
            for (int k = 0; k < TOPK; k++) insert5(tv, tix, ov[k], oi[k]);
        }
        if (tid == 0) {
            #pragma unroll
            for (int k = 0; k < TOPK; k++) { s_topv[k] = tv[k]; s_topi[k] = tix[k]; }
        }
    }
    __syncthreads();

    // softmax over top-5 (redundant per thread; s_topv[0] is the max)
    float w[TOPK];
    int   ti[TOPK];
    float m = s_topv[0];
    float sum = 0.0f;
    #pragma unroll
    for (int k = 0; k < TOPK; k++) {
        w[k] = expf(s_topv[k] - m);
        sum += w[k];
        ti[k] = s_topi[k];
    }
    float inv = 1.0f / sum;
    #pragma unroll
    for (int k = 0; k < TOPK; k++) w[k] *= inv;

    // weighted combine
    for (int d = tid; d < DIM; d += 256) {
        float acc = 0.0f;
        #pragma unroll
        for (int k = 0; k < TOPK; k++) {
            acc = fmaf(w[k], __ldg(&pool[(size_t)ti[k] * DIM + d]), acc);
        }
        out[(size_t)row * DIM + d] = acc;
    }
}

// ---------------------------------------------------------------------------
extern "C" void kernel_launch(void* const* d_in, const int* in_sizes, int n_in,
                              void* d_out, int out_size)
{
    const float* V    = (const float*)d_in[0];  // [16384, 768]
    const float* W    = (const float*)d_in[1];  // [8192, 768]
    const float* bias = (const float*)d_in[2];  // [8192]
    const float* pool = (const float*)d_in[3];  // [8192, 768]
    float* out = (float*)d_out;                 // [16384, 768]

    dim3 gemm_grid(NPROMPT / BN, B_ROWS / BM);  // (64, 128)
    gemm_topk_kernel<<<gemm_grid, 256>>>(V, W, bias);

    merge_combine_kernel<<<B_ROWS, 256>>>(pool, out);
}

// round 4
// speedup vs baseline: 1.1574x; 1.1574x over previous
#include <cuda_runtime.h>
#include <cuda_bf16.h>
#include <math_constants.h>
#include <cstdint>

#define B_ROWS   16384
#define DIM      768
#define NPROMPT  8192
#define TOPK     5
#define TOPC     12          // candidates rescored exactly per row
#define NTILE    64          // NPROMPT / 128

#define BM 128
#define BN 128
#define CHUNK    32                  // K elements per pipeline stage
#define NSTEPS   (DIM / CHUNK)       // 24
#define STAGES   4

// smem stage geometry: rows padded 32 -> 40 bf16 (80 B) for conflict-free LDS
#define ROW_B      80
#define A_BYTES    (128 * ROW_B)     // 10240
#define STAGE_B    (2 * A_BYTES)     // 20480 (A then B)
#define DYN_SMEM   (STAGES * STAGE_B) // 81920

// ---------------- device scratch (allocation-free) ----------------
__device__ __nv_bfloat16 g_vbf[(size_t)B_ROWS * DIM];
__device__ __nv_bfloat16 g_wbf[(size_t)NPROMPT * DIM];
__device__ float g_pval[(size_t)B_ROWS * NTILE * TOPK];
__device__ int   g_pidx[(size_t)B_ROWS * NTILE * TOPK];

// ---------------- helpers ----------------
__device__ __forceinline__ uint32_t smem_u32(const void* p) {
    uint32_t a;
    asm("{ .reg .u64 t; cvta.to.shared.u64 t, %1; cvt.u32.u64 %0, t; }"
        : "=r"(a) : "l"(p));
    return a;
}

#define CP_ASYNC16(dst, src) \
    asm volatile("cp.async.cg.shared.global [%0], [%1], 16;" :: "r"(dst), "l"(src))
#define CP_COMMIT() asm volatile("cp.async.commit_group;" ::: "memory")
#define CP_WAIT2()  asm volatile("cp.async.wait_group 2;" ::: "memory")

__device__ __forceinline__ void mma_bf16(float& c0, float& c1, float& c2, float& c3,
                                         uint32_t a0, uint32_t a1, uint32_t a2, uint32_t a3,
                                         uint32_t b0, uint32_t b1) {
    asm volatile(
        "mma.sync.aligned.m16n8k16.row.col.f32.bf16.bf16.f32 "
        "{%0,%1,%2,%3}, {%4,%5,%6,%7}, {%8,%9}, {%0,%1,%2,%3};"
        : "+f"(c0), "+f"(c1), "+f"(c2), "+f"(c3)
        : "r"(a0), "r"(a1), "r"(a2), "r"(a3), "r"(b0), "r"(b1));
}

template <int K>
__device__ __forceinline__ void insertK(float (&tv)[K], int (&tix)[K],
                                        float v, int ix)
{
    bool enter = (v > tv[K - 1]) || (v == tv[K - 1] && ix < tix[K - 1]);
    if (enter) {
        tv[K - 1] = v;  tix[K - 1] = ix;
        #pragma unroll
        for (int k = K - 1; k > 0; k--) {
            bool sw = (tv[k] > tv[k - 1]) ||
                      (tv[k] == tv[k - 1] && tix[k] < tix[k - 1]);
            if (sw) {
                float t = tv[k];  tv[k] = tv[k - 1];  tv[k - 1] = t;
                int  ti = tix[k]; tix[k] = tix[k - 1]; tix[k - 1] = ti;
            }
        }
    }
}

// ---------------------------------------------------------------------------
// Kernel 0: fp32 -> bf16 conversion of V and W
// ---------------------------------------------------------------------------
struct alignas(8) bf16x4 { __nv_bfloat16 v[4]; };

__global__ __launch_bounds__(256)
void convert_kernel(const float* __restrict__ V, const float* __restrict__ W)
{
    const size_t nv4 = (size_t)B_ROWS * DIM / 4;
    const size_t nw4 = (size_t)NPROMPT * DIM / 4;
    size_t stride = (size_t)gridDim.x * blockDim.x;
    for (size_t i = (size_t)blockIdx.x * blockDim.x + threadIdx.x;
         i < nv4 + nw4; i += stride) {
        const float4* src; bf16x4* dst; size_t j;
        if (i < nv4) { src = (const float4*)V; dst = (bf16x4*)g_vbf; j = i; }
        else         { src = (const float4*)W; dst = (bf16x4*)g_wbf; j = i - nv4; }
        float4 x = src[j];
        bf16x4 h;
        h.v[0] = __float2bfloat16(x.x);
        h.v[1] = __float2bfloat16(x.y);
        h.v[2] = __float2bfloat16(x.z);
        h.v[3] = __float2bfloat16(x.w);
        dst[j] = h;
    }
}

// ---------------------------------------------------------------------------
// Kernel 1: bf16 HMMA GEMM (scores = V@W^T + b) + fused per-row top-5 per tile
// ---------------------------------------------------------------------------
__global__ __launch_bounds__(256, 1)
void gemm_topk_mma_kernel(const float* __restrict__ bias)
{
    extern __shared__ char smem[];
    __shared__ float s_bias[BN];
    __shared__ float s_cval[128 * 4 * TOPK];   // [row][nwarp][k]
    __shared__ int   s_cidx[128 * 4 * TOPK];

    const int tid  = threadIdx.x;
    const int wid  = tid >> 5;
    const int lane = tid & 31;
    const int g    = lane >> 2;      // group id (row within 8)
    const int tig  = lane & 3;       // thread in group (col pair)
    const int wm   = wid >> 2;       // 0..1 (m warp)
    const int wn   = wid & 3;        // 0..3 (n warp)

    const int bn = blockIdx.x * BN;
    const int bm = blockIdx.y * BM;

    if (tid < BN) s_bias[tid] = bias[bn + tid];

    // cp.async assignments: thread handles rows {tid/4, tid/4+64}, chunk tid%4
    const int ldr = tid >> 2;        // 0..63
    const int ldc = tid & 3;         // 16B chunk within 64B row

    const __nv_bfloat16* Ag = g_vbf + (size_t)(bm + ldr) * DIM + ldc * 8;
    const __nv_bfloat16* Ag2 = Ag + (size_t)64 * DIM;
    const __nv_bfloat16* Bg = g_wbf + (size_t)(bn + ldr) * DIM + ldc * 8;
    const __nv_bfloat16* Bg2 = Bg + (size_t)64 * DIM;

    const uint32_t sb = smem_u32(smem);
    const uint32_t dA1 = sb + ldr * ROW_B + ldc * 16;
    const uint32_t dA2 = dA1 + 64 * ROW_B;
    const uint32_t dB1 = dA1 + A_BYTES;
    const uint32_t dB2 = dA2 + A_BYTES;

    auto load_stage = [&](int step) {
        const uint32_t so = (uint32_t)(step % STAGES) * STAGE_B;
        const size_t ko = (size_t)step * CHUNK;
        CP_ASYNC16(dA1 + so, Ag + ko);
        CP_ASYNC16(dA2 + so, Ag2 + ko);
        CP_ASYNC16(dB1 + so, Bg + ko);
        CP_ASYNC16(dB2 + so, Bg2 + ko);
    };

    // prologue: stages 0..2
    #pragma unroll
    for (int s = 0; s < STAGES - 1; s++) { load_stage(s); CP_COMMIT(); }

    float acc[4][4][4];
    #pragma unroll
    for (int i = 0; i < 4; i++)
        #pragma unroll
        for (int j = 0; j < 4; j++)
            #pragma unroll
            for (int r = 0; r < 4; r++)
                acc[i][j][r] = 0.0f;

    // fragment base addresses (per warp/lane), within a stage
    const uint32_t aFrag0 = sb + (wm * 64 + g) * ROW_B + tig * 4;
    const uint32_t bFrag0 = sb + A_BYTES + (wn * 32 + g) * ROW_B + tig * 4;

    for (int t = 0; t < NSTEPS; t++) {
        CP_WAIT2();
        __syncthreads();
        if (t + STAGES - 1 < NSTEPS) load_stage(t + STAGES - 1);
        CP_COMMIT();

        const uint32_t so = (uint32_t)(t % STAGES) * STAGE_B;
        #pragma unroll
        for (int ks = 0; ks < 2; ks++) {
            uint32_t af[4][4], bf[4][2];
            #pragma unroll
            for (int i = 0; i < 4; i++) {
                uint32_t base = aFrag0 + so + i * (16 * ROW_B) + ks * 32;
                asm volatile("ld.shared.b32 %0, [%1];"       : "=r"(af[i][0]) : "r"(base));
                asm volatile("ld.shared.b32 %0, [%1+640];"   : "=r"(af[i][1]) : "r"(base));
                asm volatile("ld.shared.b32 %0, [%1+16];"    : "=r"(af[i][2]) : "r"(base));
                asm volatile("ld.shared.b32 %0, [%1+656];"   : "=r"(af[i][3]) : "r"(base));
            }
            #pragma unroll
            for (int j = 0; j < 4; j++) {
                uint32_t base = bFrag0 + so + j * (8 * ROW_B) + ks * 32;
                asm volatile("ld.shared.b32 %0, [%1];"       : "=r"(bf[j][0]) : "r"(base));
                asm volatile("ld.shared.b32 %0, [%1+16];"    : "=r"(bf[j][1]) : "r"(base));
            }
            #pragma unroll
            for (int i = 0; i < 4; i++)
                #pragma unroll
                for (int j = 0; j < 4; j++)
                    mma_bf16(acc[i][j][0], acc[i][j][1], acc[i][j][2], acc[i][j][3],
                             af[i][0], af[i][1], af[i][2], af[i][3],
                             bf[j][0], bf[j][1]);
        }
        __syncthreads();
    }

    // ---- epilogue: bias + per-row top-5 over this 128-col tile ----
    const unsigned FULL = 0xffffffffu;
    #pragma unroll
    for (int i = 0; i < 4; i++) {
        #pragma unroll
        for (int h = 0; h < 2; h++) {
            const int row_local = wm * 64 + i * 16 + h * 8 + g;
            float tv[TOPK]; int tix[TOPK];
            #pragma unroll
            for (int k = 0; k < TOPK; k++) { tv[k] = -CUDART_INF_F; tix[k] = 0x7fffffff; }
            #pragma unroll
            for (int j = 0; j < 4; j++) {
                int c0 = wn * 32 + j * 8 + tig * 2;
                insertK<TOPK>(tv, tix, acc[i][j][2 * h]     + s_bias[c0],     bn + c0);
                insertK<TOPK>(tv, tix, acc[i][j][2 * h + 1] + s_bias[c0 + 1], bn + c0 + 1);
            }
            // merge across the 4 lanes of the group (offsets 1, 2)
            #pragma unroll
            for (int off = 1; off < 4; off <<= 1) {
                float ov[TOPK]; int oi[TOPK];
                #pragma unroll
                for (int k = 0; k < TOPK; k++) {
                    ov[k] = __shfl_xor_sync(FULL, tv[k], off);
                    oi[k] = __shfl_xor_sync(FULL, tix[k], off);
                }
                #pragma unroll
                for (int k = 0; k < TOPK; k++) insertK<TOPK>(tv, tix, ov[k], oi[k]);
            }
            if (tig == 0) {
                int base = (row_local * 4 + wn) * TOPK;
                #pragma unroll
                for (int k = 0; k < TOPK; k++) {
                    s_cval[base + k] = tv[k];
                    s_cidx[base + k] = tix[k];
                }
            }
        }
    }
    __syncthreads();

    if (tid < 128) {
        float tv[TOPK]; int tix[TOPK];
        #pragma unroll
        for (int k = 0; k < TOPK; k++) { tv[k] = -CUDART_INF_F; tix[k] = 0x7fffffff; }
        #pragma unroll
        for (int w = 0; w < 4; w++) {
            int base = (tid * 4 + w) * TOPK;
            #pragma unroll
            for (int k = 0; k < TOPK; k++)
                insertK<TOPK>(tv, tix, s_cval[base + k], s_cidx[base + k]);
        }
        size_t gbase = ((size_t)(bm + tid) * NTILE + blockIdx.x) * TOPK;
        #pragma unroll
        for (int k = 0; k < TOPK; k++) {
            g_pval[gbase + k] = tv[k];
            g_pidx[gbase + k] = tix[k];
        }
    }
}

// ---------------------------------------------------------------------------
// Kernel 2: merge 64x5 -> top-12, exact fp32 rescore, top-5, softmax, combine
// ---------------------------------------------------------------------------
__global__ __launch_bounds__(256)
void merge_rescore_kernel(const float* __restrict__ V,
                          const float* __restrict__ W,
                          const float* __restrict__ bias,
                          const float* __restrict__ pool,
                          float* __restrict__ out)
{
    const int row = blockIdx.x;
    const int tid = threadIdx.x;
    const int wid = tid >> 5;
    const int lane = tid & 31;

    __shared__ float s_v[DIM];
    __shared__ int   s_cidx[TOPC];
    __shared__ float s_cval[TOPC];

    // stage V row in smem
    for (int d = tid; d < DIM; d += 256) s_v[d] = V[(size_t)row * DIM + d];

    // warp 0: merge approximate partials into top-12 candidates
    if (wid == 0) {
        const unsigned FULL = 0xffffffffu;
        float tv[TOPC]; int tix[TOPC];
        #pragma unroll
        for (int k = 0; k < TOPC; k++) { tv[k] = -CUDART_INF_F; tix[k] = 0x7fffffff; }
        size_t rbase = (size_t)row * NTILE * TOPK;
        #pragma unroll
        for (int h = 0; h < 2; h++) {
            size_t base = rbase + (size_t)(lane + h * 32) * TOPK;
            #pragma unroll
            for (int k = 0; k < TOPK; k++)
                insertK<TOPC>(tv, tix, g_pval[base + k], g_pidx[base + k]);
        }
        #pragma unroll
        for (int off = 1; off < 32; off <<= 1) {
            float ov[TOPC]; int oi[TOPC];
            #pragma unroll
            for (int k = 0; k < TOPC; k++) {
                ov[k] = __shfl_xor_sync(FULL, tv[k], off);
                oi[k] = __shfl_xor_sync(FULL, tix[k], off);
            }
            #pragma unroll
            for (int k = 0; k < TOPC; k++) insertK<TOPC>(tv, tix, ov[k], oi[k]);
        }
        if (lane < TOPC) s_cidx[lane] = tix[lane];
    }
    __syncthreads();

    // warps 0-7: exact rescoring; warp w does candidates w and w+8 (w<4)
    #pragma unroll
    for (int h = 0; h < 2; h++) {
        int cand_slot = wid + h * 8;
        if (cand_slot < TOPC) {
            int cand = s_cidx[cand_slot];
            const float* wrow = W + (size_t)cand * DIM;
            float p = 0.0f;
            #pragma unroll
            for (int it = 0; it < DIM / 32; it++) {
                int k = lane + it * 32;
                p = fmaf(s_v[k], __ldg(&wrow[k]), p);
            }
            #pragma unroll
            for (int off = 16; off > 0; off >>= 1)
                p += __shfl_xor_sync(0xffffffffu, p, off);
            if (lane == 0) s_cval[cand_slot] = p + __ldg(&bias[cand]);
        }
    }
    __syncthreads();

    // exact top-5 of the 12 (redundant per thread)
    float tv[TOPK]; int tix[TOPK];
    #pragma unroll
    for (int k = 0; k < TOPK; k++) { tv[k] = -CUDART_INF_F; tix[k] = 0x7fffffff; }
    #pragma unroll
    for (int k = 0; k < TOPC; k++) insertK<TOPK>(tv, tix, s_cval[k], s_cidx[k]);

    float w[TOPK];
    float m = tv[0], sum = 0.0f;
    #pragma unroll
    for (int k = 0; k < TOPK; k++) { w[k] = expf(tv[k] - m); sum += w[k]; }
    float inv = 1.0f / sum;
    #pragma unroll
    for (int k = 0; k < TOPK; k++) w[k] *= inv;

    for (int d = tid; d < DIM; d += 256) {
        float acc = 0.0f;
        #pragma unroll
        for (int k = 0; k < TOPK; k++)
            acc = fmaf(w[k], __ldg(&pool[(size_t)tix[k] * DIM + d]), acc);
        out[(size_t)row * DIM + d] = acc;
    }
}

// ---------------------------------------------------------------------------
extern "C" void kernel_launch(void* const* d_in, const int* in_sizes, int n_in,
                              void* d_out, int out_size)
{
    const float* V    = (const float*)d_in[0];  // [16384, 768]
    const float* W    = (const float*)d_in[1];  // [8192, 768]
    const float* bias = (const float*)d_in[2];  // [8192]
    const float* pool = (const float*)d_in[3];  // [8192, 768]
    float* out = (float*)d_out;                 // [16384, 768]

    static bool attr_done = false;
    if (!attr_done) {
        cudaFuncSetAttribute(gemm_topk_mma_kernel,
                             cudaFuncAttributeMaxDynamicSharedMemorySize, DYN_SMEM);
        attr_done = true;
    }

    convert_kernel<<<2048, 256>>>(V, W);

    dim3 grid(NPROMPT / BN, B_ROWS / BM);   // (64, 128)
    gemm_topk_mma_kernel<<<grid, 256, DYN_SMEM>>>(bias);

    merge_rescore_kernel<<<B_ROWS, 256>>>(V, W, bias, pool, out);
}